// round 2
// baseline (speedup 1.0000x reference)
#include <cuda_runtime.h>

// Problem constants
#define BB 512
#define NN 256
#define DD 128
#define BND ((size_t)BB * NN * DD)

static __device__ float g_W1T[DD * DD];   // [d'][d] = sum_e Wq1[e,d] * Wk1[e,d']
static __device__ float g_W2T[DD * DD];   // [d'][d] = sum_e Wq2[e,d] * Wk2[e,d']
static __device__ float g_T[BND];         // scratch: T, then K2C (reused)
static __device__ unsigned char g_mask[BB * NN];
static __device__ int g_mwidth1;          // 1 if mask buffer is 1-byte elems

#define SCALE 0.08838834764831845f  // 1/sqrt(128)

// ---------------------------------------------------------------------------
// Mask dtype detection: inspect first 128KB (in-bounds for every layout).
// A word that is not 0, 1, or 0x3F800000 can only occur in a uint8 0/1 array.
// ---------------------------------------------------------------------------
__global__ void detect_mask_kernel(const unsigned int* __restrict__ m) {
    __shared__ int red[256];
    int tid = threadIdx.x;
    int p = 0;
    for (int i = tid; i < (BB * NN) / 4; i += 256) {
        unsigned int w = m[i];
        if (w != 0u && w != 1u && w != 0x3F800000u) p = 1;
    }
    red[tid] = p;
    __syncthreads();
    for (int s = 128; s > 0; s >>= 1) {
        if (tid < s) red[tid] |= red[tid + s];
        __syncthreads();
    }
    if (tid == 0) g_mwidth1 = red[0];
}

__global__ void decode_mask_kernel(const void* __restrict__ m) {
    int i = blockIdx.x * 256 + threadIdx.x;
    if (i >= BB * NN) return;
    unsigned char v;
    if (g_mwidth1)
        v = (((const unsigned char*)m)[i] != 0);
    else
        v = (((const unsigned int*)m)[i] != 0u);
    g_mask[i] = v;
}

// ---------------------------------------------------------------------------
// K0: precompute the two 128x128 contracted weight matrices.
// out[a*128 + c] = sum_k X[k*128 + c] * Y[k*128 + a]
// ---------------------------------------------------------------------------
__global__ void prep_w_kernel(const float* __restrict__ Wq1, const float* __restrict__ Wk1,
                              const float* __restrict__ Wq2, const float* __restrict__ Wk2) {
    int a = blockIdx.x;       // 0..127
    int c = threadIdx.x;      // 0..127
    const float* X = (blockIdx.y == 0) ? Wq1 : Wq2;
    const float* Y = (blockIdx.y == 0) ? Wk1 : Wk2;
    float* out = (blockIdx.y == 0) ? g_W1T : g_W2T;
    float acc = 0.f;
#pragma unroll 8
    for (int k = 0; k < DD; k++)
        acc = fmaf(X[k * DD + c], Y[k * DD + a], acc);
    out[a * DD + c] = acc;
}

// ---------------------------------------------------------------------------
// K1/K3: C(=g_T)[n][e] = sum_d A[n][d] * W[d][e]   (W = g_W1T or g_W2T)
// Tile: 64 rows x 128 cols per block, 256 threads, 4x8 micro-tile.
// smem: sA [128][68] transposed A, sW [128][132] natural W.
// ---------------------------------------------------------------------------
__global__ __launch_bounds__(256) void gemm_nw_kernel(const float* __restrict__ A, int wsel) {
    extern __shared__ float sm[];
    float* sA = sm;                 // [d][n] stride 68
    float* sW = sm + 128 * 68;      // [d][e] stride 132
    const float* W = (wsel == 0) ? g_W1T : g_W2T;
    int tid = threadIdx.x;
    size_t n0 = (size_t)blockIdx.x * 64;

    // load W natural (rows of 128 floats -> stride 132)
    for (int f = tid; f < 4096; f += 256) {
        int r = f >> 5, c4 = f & 31;
        float4 v = ((const float4*)W)[f];
        *(float4*)&sW[r * 132 + c4 * 4] = v;
    }
    // load A transposed: units of (4 n x 32 d)
    {
        int w = tid >> 5, l = tid & 31;
        for (int u = w; u < 64; u += 8) {
            int ng = u & 15, dg = u >> 4;
            int d = dg * 32 + l;
            const float* base = A + (n0 + (size_t)ng * 4) * DD + d;
            float4 v;
            v.x = base[0];
            v.y = base[DD];
            v.z = base[2 * DD];
            v.w = base[3 * DD];
            *(float4*)&sA[d * 68 + ng * 4] = v;
        }
    }
    __syncthreads();

    int ty = tid >> 4, tx = tid & 15;
    float acc[4][8];
#pragma unroll
    for (int r = 0; r < 4; r++)
#pragma unroll
        for (int c = 0; c < 8; c++) acc[r][c] = 0.f;

#pragma unroll 8
    for (int d = 0; d < 128; d++) {
        float4 af = *(const float4*)&sA[d * 68 + ty * 4];
        float4 b0 = *(const float4*)&sW[d * 132 + tx * 8];
        float4 b1 = *(const float4*)&sW[d * 132 + tx * 8 + 4];
        float av[4] = {af.x, af.y, af.z, af.w};
        float bv[8] = {b0.x, b0.y, b0.z, b0.w, b1.x, b1.y, b1.z, b1.w};
#pragma unroll
        for (int r = 0; r < 4; r++)
#pragma unroll
            for (int c = 0; c < 8; c++)
                acc[r][c] = fmaf(av[r], bv[c], acc[r][c]);
    }
#pragma unroll
    for (int r = 0; r < 4; r++) {
        float* dst = g_T + (n0 + ty * 4 + r) * DD + tx * 8;
        *(float4*)dst = make_float4(acc[r][0], acc[r][1], acc[r][2], acc[r][3]);
        *(float4*)(dst + 4) = make_float4(acc[r][4], acc[r][5], acc[r][6], acc[r][7]);
    }
}

// ---------------------------------------------------------------------------
// K2: alpha[n] = SCALE * dot(S[n], T[n]); sat_out = s + alpha*(m - s)
// One warp per node, 8 nodes per block.
// ---------------------------------------------------------------------------
__global__ __launch_bounds__(256) void stage1_kernel(const float* __restrict__ M,
                                                     const float* __restrict__ S,
                                                     float* __restrict__ SO) {
    int w = threadIdx.x >> 5, l = threadIdx.x & 31;
    size_t n = (size_t)blockIdx.x * 8 + w;
    const float* mrow = M + n * DD;
    const float* srow = S + n * DD;
    const float* trow = g_T + n * DD;
    float sv[4];
    float p = 0.f;
#pragma unroll
    for (int k = 0; k < 4; k++) {
        int d = k * 32 + l;
        sv[k] = srow[d];
        p = fmaf(sv[k], trow[d], p);
    }
#pragma unroll
    for (int off = 16; off > 0; off >>= 1)
        p += __shfl_xor_sync(0xffffffffu, p, off);
    float alpha = p * SCALE;
#pragma unroll
    for (int k = 0; k < 4; k++) {
        int d = k * 32 + l;
        SO[n * DD + d] = fmaf(alpha, mrow[d] - sv[k], sv[k]);
    }
}

// ---------------------------------------------------------------------------
// K4: fused attention per (batch b, i-tile of 64 mirror rows)
//   beta[i][j] = SCALE * sum_d M[b][i][d] * K2C[b][j][d]   (K2C in g_T)
//   mask, softmax over j, then out[i][d] = sum_j P[i][j] * M[b][j][d]
// smem: sQ [128][68] (M_i transposed), sK [128][132] (stream buffer),
//       sB [64][260] (beta/prob tile)
// ---------------------------------------------------------------------------
__global__ __launch_bounds__(256) void attn_kernel(const float* __restrict__ M,
                                                   float* __restrict__ O) {
    extern __shared__ float sm[];
    float* sQ = sm;                              // [d][i] stride 68
    float* sK = sm + 128 * 68;                   // stride 132
    float* sB = sm + 128 * 68 + 128 * 132;       // [i][j] stride 260
    __shared__ unsigned char smask[NN];

    int tid = threadIdx.x;
    int b = blockIdx.y;
    int i0 = blockIdx.x * 64;
    const float* Mb = M + (size_t)b * NN * DD;
    const float* Kb = g_T + (size_t)b * NN * DD;

    smask[tid] = g_mask[(size_t)b * NN + tid];

    int w = tid >> 5, l = tid & 31;
    // sQ = transpose of M[b][i0..i0+64][:]
    for (int u = w; u < 64; u += 8) {
        int ig = u & 15, dg = u >> 4;
        int d = dg * 32 + l;
        const float* base = Mb + (size_t)(i0 + ig * 4) * DD + d;
        float4 v;
        v.x = base[0]; v.y = base[DD]; v.z = base[2 * DD]; v.w = base[3 * DD];
        *(float4*)&sQ[d * 68 + ig * 4] = v;
    }
    __syncthreads();

    int ty = tid >> 4, tx = tid & 15;
    float acc[4][8];

    // ---- GEMM1: beta tile, two j-chunks of 128 ----
    for (int jc = 0; jc < 2; jc++) {
        for (int u = w; u < 128; u += 8) {
            int jg = u & 31, dg = u >> 5;
            int d = dg * 32 + l;
            const float* base = Kb + (size_t)(jc * 128 + jg * 4) * DD + d;
            float4 v;
            v.x = base[0]; v.y = base[DD]; v.z = base[2 * DD]; v.w = base[3 * DD];
            *(float4*)&sK[d * 132 + jg * 4] = v;
        }
        __syncthreads();
#pragma unroll
        for (int r = 0; r < 4; r++)
#pragma unroll
            for (int c = 0; c < 8; c++) acc[r][c] = 0.f;
#pragma unroll 8
        for (int d = 0; d < 128; d++) {
            float4 af = *(const float4*)&sQ[d * 68 + ty * 4];
            float4 b0 = *(const float4*)&sK[d * 132 + tx * 8];
            float4 b1 = *(const float4*)&sK[d * 132 + tx * 8 + 4];
            float av[4] = {af.x, af.y, af.z, af.w};
            float bv[8] = {b0.x, b0.y, b0.z, b0.w, b1.x, b1.y, b1.z, b1.w};
#pragma unroll
            for (int r = 0; r < 4; r++)
#pragma unroll
                for (int c = 0; c < 8; c++)
                    acc[r][c] = fmaf(av[r], bv[c], acc[r][c]);
        }
#pragma unroll
        for (int r = 0; r < 4; r++) {
            float* dst = &sB[(ty * 4 + r) * 260 + jc * 128 + tx * 8];
            *(float4*)dst = make_float4(acc[r][0] * SCALE, acc[r][1] * SCALE,
                                        acc[r][2] * SCALE, acc[r][3] * SCALE);
            *(float4*)(dst + 4) = make_float4(acc[r][4] * SCALE, acc[r][5] * SCALE,
                                              acc[r][6] * SCALE, acc[r][7] * SCALE);
        }
        __syncthreads();
    }

    // ---- masked softmax over each of the 64 rows (one warp per row) ----
    for (int rr = w; rr < 64; rr += 8) {
        float* row = sB + rr * 260;
        float v[8], mx = -3.0e38f;
#pragma unroll
        for (int k = 0; k < 8; k++) {
            int j = l + k * 32;
            float x = row[j];
            v[k] = smask[j] ? x : -3.0e38f;
            mx = fmaxf(mx, v[k]);
        }
#pragma unroll
        for (int off = 16; off > 0; off >>= 1)
            mx = fmaxf(mx, __shfl_xor_sync(0xffffffffu, mx, off));
        float s = 0.f;
#pragma unroll
        for (int k = 0; k < 8; k++) { v[k] = __expf(v[k] - mx); s += v[k]; }
#pragma unroll
        for (int off = 16; off > 0; off >>= 1)
            s += __shfl_xor_sync(0xffffffffu, s, off);
        float inv = __fdividef(1.f, s);
#pragma unroll
        for (int k = 0; k < 8; k++) row[l + k * 32] = v[k] * inv;
    }
    __syncthreads();

    // ---- GEMM2: out = P @ M_b, two k-chunks of 128 ----
#pragma unroll
    for (int r = 0; r < 4; r++)
#pragma unroll
        for (int c = 0; c < 8; c++) acc[r][c] = 0.f;

    for (int kc = 0; kc < 2; kc++) {
        const float4* src = (const float4*)(Mb + (size_t)kc * 128 * DD);
        for (int f = tid; f < 4096; f += 256) {
            int r = f >> 5, c4 = f & 31;
            *(float4*)&sK[r * 132 + c4 * 4] = src[f];
        }
        __syncthreads();
#pragma unroll 8
        for (int k = 0; k < 128; k++) {
            float av[4];
#pragma unroll
            for (int r = 0; r < 4; r++) av[r] = sB[(ty * 4 + r) * 260 + kc * 128 + k];
            float4 b0 = *(const float4*)&sK[k * 132 + tx * 8];
            float4 b1 = *(const float4*)&sK[k * 132 + tx * 8 + 4];
            float bv[8] = {b0.x, b0.y, b0.z, b0.w, b1.x, b1.y, b1.z, b1.w};
#pragma unroll
            for (int r = 0; r < 4; r++)
#pragma unroll
                for (int c = 0; c < 8; c++)
                    acc[r][c] = fmaf(av[r], bv[c], acc[r][c]);
        }
        __syncthreads();
    }

    float* Ob = O + ((size_t)b * NN + i0) * DD;
#pragma unroll
    for (int r = 0; r < 4; r++) {
        float* dst = Ob + (size_t)(ty * 4 + r) * DD + tx * 8;
        *(float4*)dst = make_float4(acc[r][0], acc[r][1], acc[r][2], acc[r][3]);
        *(float4*)(dst + 4) = make_float4(acc[r][4], acc[r][5], acc[r][6], acc[r][7]);
    }
}

// ---------------------------------------------------------------------------
extern "C" void kernel_launch(void* const* d_in, const int* in_sizes, int n_in,
                              void* d_out, int out_size) {
    (void)in_sizes; (void)n_in; (void)out_size;
    const float* mirror    = (const float*)d_in[0];
    const float* satellite = (const float*)d_in[1];
    const void*  mask      = d_in[2];
    const float* Wq1 = (const float*)d_in[3];
    const float* Wk1 = (const float*)d_in[4];
    const float* Wq2 = (const float*)d_in[5];
    const float* Wk2 = (const float*)d_in[6];
    float* sat_out = (float*)d_out;                 // first  B*N*D floats
    float* mir_out = (float*)d_out + BND;           // second B*N*D floats

    const int smemG = (128 * 68 + 128 * 132) * 4;                 // 102400
    const int smemA = (128 * 68 + 128 * 132 + 64 * 260) * 4;      // 168960
    cudaFuncSetAttribute(gemm_nw_kernel, cudaFuncAttributeMaxDynamicSharedMemorySize, smemG);
    cudaFuncSetAttribute(attn_kernel,    cudaFuncAttributeMaxDynamicSharedMemorySize, smemA);

    // Mask canonicalization (dtype-agnostic)
    detect_mask_kernel<<<1, 256>>>((const unsigned int*)mask);
    decode_mask_kernel<<<(BB * NN + 255) / 256, 256>>>(mask);

    // K0: W1T/W2T
    prep_w_kernel<<<dim3(128, 2), 128>>>(Wq1, Wk1, Wq2, Wk2);
    // K1: T = M @ W1T  -> g_T
    gemm_nw_kernel<<<(BB * NN) / 64, 256, smemG>>>(mirror, 0);
    // K2: alpha + sat_out
    stage1_kernel<<<(BB * NN) / 8, 256>>>(mirror, satellite, sat_out);
    // K3: K2C = sat_out @ W2T -> g_T (overwrites T)
    gemm_nw_kernel<<<(BB * NN) / 64, 256, smemG>>>(sat_out, 1);
    // K4: fused masked attention -> mir_out
    attn_kernel<<<dim3(NN / 64, BB), 256, smemA>>>(mirror, mir_out);
}

// round 4
// speedup vs baseline: 1.3585x; 1.3585x over previous
#include <cuda_runtime.h>
#include <cuda_bf16.h>
#include <cstdint>

// Problem constants
#define BB 512
#define NN 256
#define DD 128
#define BND ((size_t)BB * NN * DD)

static __device__ float g_W1T[DD * DD];   // SCALE * (Wq1^T Wk1) in [d][e] order
static __device__ float g_W2T[DD * DD];   // SCALE * (Wq2^T Wk2)
static __device__ float g_T[BND];         // scratch: T, then K2C (reused)
static __device__ unsigned char g_mask[BB * NN];
static __device__ int g_mwidth1;

#define SCALE 0.08838834764831845f  // 1/sqrt(128)

// ============================ PTX helpers ==================================
__device__ __forceinline__ uint32_t smem_u32(const void* p) {
    uint32_t a;
    asm("{ .reg .u64 t; cvta.to.shared.u64 t, %1; cvt.u32.u64 %0, t; }" : "=r"(a) : "l"(p));
    return a;
}

#define LDSM_X4(r, a) \
    asm volatile("ldmatrix.sync.aligned.m8n8.x4.shared.b16 {%0,%1,%2,%3}, [%4];" \
        : "=r"((r)[0]), "=r"((r)[1]), "=r"((r)[2]), "=r"((r)[3]) : "r"(a))
#define LDSM_X4T(r, a) \
    asm volatile("ldmatrix.sync.aligned.m8n8.x4.trans.shared.b16 {%0,%1,%2,%3}, [%4];" \
        : "=r"((r)[0]), "=r"((r)[1]), "=r"((r)[2]), "=r"((r)[3]) : "r"(a))

__device__ __forceinline__ void mma_bf16(float* c, const uint32_t* a, uint32_t b0, uint32_t b1) {
    asm volatile(
        "mma.sync.aligned.m16n8k16.row.col.f32.bf16.bf16.f32 "
        "{%0,%1,%2,%3}, {%4,%5,%6,%7}, {%8,%9}, {%0,%1,%2,%3};"
        : "+f"(c[0]), "+f"(c[1]), "+f"(c[2]), "+f"(c[3])
        : "r"(a[0]), "r"(a[1]), "r"(a[2]), "r"(a[3]), "r"(b0), "r"(b1));
}

// split a float pair into bf16x2 hi and lo words
__device__ __forceinline__ void split_pack(float x, float y, uint32_t& h, uint32_t& l) {
    __nv_bfloat16 hx = __float2bfloat16(x);
    __nv_bfloat16 hy = __float2bfloat16(y);
    __nv_bfloat16 lx = __float2bfloat16(x - __bfloat162float(hx));
    __nv_bfloat16 ly = __float2bfloat16(y - __bfloat162float(hy));
    __nv_bfloat162 hh; hh.x = hx; hh.y = hy;
    __nv_bfloat162 ll; ll.x = lx; ll.y = ly;
    h = *(uint32_t*)&hh;
    l = *(uint32_t*)&ll;
}

// ======================= mask canonicalization =============================
__global__ void detect_mask_kernel(const unsigned int* __restrict__ m) {
    __shared__ int red[256];
    int tid = threadIdx.x;
    int p = 0;
    for (int i = tid; i < (BB * NN) / 4; i += 256) {
        unsigned int w = m[i];
        if (w != 0u && w != 1u && w != 0x3F800000u) p = 1;
    }
    red[tid] = p;
    __syncthreads();
    for (int s = 128; s > 0; s >>= 1) {
        if (tid < s) red[tid] |= red[tid + s];
        __syncthreads();
    }
    if (tid == 0) g_mwidth1 = red[0];
}

__global__ void decode_mask_kernel(const void* __restrict__ m) {
    int i = blockIdx.x * 256 + threadIdx.x;
    if (i >= BB * NN) return;
    unsigned char v;
    if (g_mwidth1) v = (((const unsigned char*)m)[i] != 0);
    else           v = (((const unsigned int*)m)[i] != 0u);
    g_mask[i] = v;
}

// ======================= weight contraction (scaled) =======================
__global__ void prep_w_kernel(const float* __restrict__ Wq1, const float* __restrict__ Wk1,
                              const float* __restrict__ Wq2, const float* __restrict__ Wk2) {
    int a = blockIdx.x, c = threadIdx.x;
    const float* X = (blockIdx.y == 0) ? Wq1 : Wq2;
    const float* Y = (blockIdx.y == 0) ? Wk1 : Wk2;
    float* out = (blockIdx.y == 0) ? g_W1T : g_W2T;
    float acc = 0.f;
#pragma unroll 8
    for (int k = 0; k < DD; k++)
        acc = fmaf(X[k * DD + c], Y[k * DD + a], acc);
    out[a * DD + c] = acc * SCALE;
}

// ======================= projection GEMM (fp32 FMA, validated) =============
__global__ __launch_bounds__(256) void gemm_nw_kernel(const float* __restrict__ A, int wsel) {
    extern __shared__ float sm[];
    float* sA = sm;
    float* sW = sm + 128 * 68;
    const float* W = (wsel == 0) ? g_W1T : g_W2T;
    int tid = threadIdx.x;
    size_t n0 = (size_t)blockIdx.x * 64;

    for (int f = tid; f < 4096; f += 256) {
        int r = f >> 5, c4 = f & 31;
        float4 v = ((const float4*)W)[f];
        *(float4*)&sW[r * 132 + c4 * 4] = v;
    }
    {
        int w = tid >> 5, l = tid & 31;
        for (int u = w; u < 64; u += 8) {
            int ng = u & 15, dg = u >> 4;
            int d = dg * 32 + l;
            const float* base = A + (n0 + (size_t)ng * 4) * DD + d;
            float4 v;
            v.x = base[0]; v.y = base[DD]; v.z = base[2 * DD]; v.w = base[3 * DD];
            *(float4*)&sA[d * 68 + ng * 4] = v;
        }
    }
    __syncthreads();

    int ty = tid >> 4, tx = tid & 15;
    float acc[4][8];
#pragma unroll
    for (int r = 0; r < 4; r++)
#pragma unroll
        for (int c = 0; c < 8; c++) acc[r][c] = 0.f;

#pragma unroll 8
    for (int d = 0; d < 128; d++) {
        float4 af = *(const float4*)&sA[d * 68 + ty * 4];
        float4 b0 = *(const float4*)&sW[d * 132 + tx * 8];
        float4 b1 = *(const float4*)&sW[d * 132 + tx * 8 + 4];
        float av[4] = {af.x, af.y, af.z, af.w};
        float bv[8] = {b0.x, b0.y, b0.z, b0.w, b1.x, b1.y, b1.z, b1.w};
#pragma unroll
        for (int r = 0; r < 4; r++)
#pragma unroll
            for (int c = 0; c < 8; c++)
                acc[r][c] = fmaf(av[r], bv[c], acc[r][c]);
    }
#pragma unroll
    for (int r = 0; r < 4; r++) {
        float* dst = g_T + (n0 + ty * 4 + r) * DD + tx * 8;
        *(float4*)dst = make_float4(acc[r][0], acc[r][1], acc[r][2], acc[r][3]);
        *(float4*)(dst + 4) = make_float4(acc[r][4], acc[r][5], acc[r][6], acc[r][7]);
    }
}

// ======================= stage 1 (gate + sat_out) ==========================
__global__ __launch_bounds__(256) void stage1_kernel(const float* __restrict__ M,
                                                     const float* __restrict__ S,
                                                     float* __restrict__ SO) {
    int w = threadIdx.x >> 5, l = threadIdx.x & 31;
    size_t n = (size_t)blockIdx.x * 8 + w;
    const float* mrow = M + n * DD;
    const float* srow = S + n * DD;
    const float* trow = g_T + n * DD;
    float sv[4];
    float p = 0.f;
#pragma unroll
    for (int k = 0; k < 4; k++) {
        int d = k * 32 + l;
        sv[k] = srow[d];
        p = fmaf(sv[k], trow[d], p);
    }
#pragma unroll
    for (int off = 16; off > 0; off >>= 1)
        p += __shfl_xor_sync(0xffffffffu, p, off);
    float alpha = p;  // SCALE folded into W1T
#pragma unroll
    for (int k = 0; k < 4; k++) {
        int d = k * 32 + l;
        SO[n * DD + d] = fmaf(alpha, mrow[d] - sv[k], sv[k]);
    }
}

// ======================= mma.sync fused attention ==========================
// CTA = (batch b, i-tile of 64 rows). 256 threads = 8 warps, 4m x 2n grid.
// Phase A smem: Qh[64][136], Ql, Kh[256][136], Kl   (bf16, 272 B rows)
// Phase B smem: Ph[64][264], Pl (528 B rows), Vh[256][136], Vl
#define ST_K   136      // elems (272 B rows)
#define ST_P   264      // elems (528 B rows)
#define SM_QH  0
#define SM_QL  17408
#define SM_KH  34816
#define SM_KL  104448
#define SM_PH  0
#define SM_PL  33792
#define SM_VH  67584
#define SM_VL  137216
#define SM_BIAS 206848
#define SM_RED  207872
#define SMEM_ATTN 208896

// convert fp32 rows -> bf16 hi/lo smem tile with stride ST_K (rows*128 elems)
__device__ __forceinline__ void cvt_rows(const float* __restrict__ src,
                                         char* dh, char* dl, int tid, int nf2) {
    for (int idx = tid; idx < nf2; idx += 256) {
        int row = idx >> 6, c2 = idx & 63;
        float2 v = ((const float2*)src)[idx];
        uint32_t h, l;
        split_pack(v.x, v.y, h, l);
        uint32_t off = row * (ST_K * 2) + c2 * 4;
        *(uint32_t*)(dh + off) = h;
        *(uint32_t*)(dl + off) = l;
    }
}

__global__ __launch_bounds__(256, 1)
void attn_mma_kernel(const float* __restrict__ M, float* __restrict__ O) {
    extern __shared__ char smem[];
    uint32_t sbase = smem_u32(smem);

    int tid = threadIdx.x;
    int w = tid >> 5, l = tid & 31;
    int g = l >> 2, t = l & 3;
    int mw = w & 3, nw = w >> 2;
    int b = blockIdx.y;
    int i0 = blockIdx.x * 64;
    const float* Mb = M + (size_t)b * NN * DD;
    const float* Kb = g_T + (size_t)b * NN * DD;

    float* bias = (float*)(smem + SM_BIAS);
    float* red = (float*)(smem + SM_RED);
    bias[tid] = g_mask[(size_t)b * NN + tid] ? 0.f : -1e30f;

    // --- convert Q (64 rows) and K (256 rows) to split bf16 ---
    cvt_rows(Mb + (size_t)i0 * DD, smem + SM_QH, smem + SM_QL, tid, 64 * 64);
    cvt_rows(Kb, smem + SM_KH, smem + SM_KL, tid, 256 * 64);
    __syncthreads();

    // --- beta GEMM: warp tile 16m x 128n, k = 128 (8 steps), 3 split terms ---
    int r0 = 16 * mw;               // A row base (within 64-row tile)
    int n0 = 128 * nw;              // B col base
    float acc[16][4];
#pragma unroll
    for (int i = 0; i < 16; i++)
#pragma unroll
        for (int j = 0; j < 4; j++) acc[i][j] = 0.f;

    uint32_t aRow = (uint32_t)(r0 + (l & 15));
    uint32_t aColHalf = (uint32_t)((l >> 4) << 3);
    uint32_t bRowBase = (uint32_t)(((l >> 4) << 3) + (l & 7));
    uint32_t bColHalf = (uint32_t)(((l >> 3) & 1) << 3);

#pragma unroll 1
    for (int ks = 0; ks < 8; ks++) {
        int k0 = 16 * ks;
        uint32_t aaddr = sbase + SM_QH + aRow * (ST_K * 2) + (k0 + aColHalf) * 2;
        uint32_t aH[4], aL[4];
        LDSM_X4(aH, aaddr);
        LDSM_X4(aL, aaddr + (SM_QL - SM_QH));
#pragma unroll
        for (int np = 0; np < 8; np++) {
            uint32_t baddr = sbase + SM_KH +
                (uint32_t)(n0 + 16 * np + bRowBase) * (ST_K * 2) + (k0 + bColHalf) * 2;
            uint32_t bH[4], bL[4];
            LDSM_X4(bH, baddr);
            LDSM_X4(bL, baddr + (SM_KL - SM_KH));
            mma_bf16(acc[2 * np],     aH, bH[0], bH[1]);
            mma_bf16(acc[2 * np],     aH, bL[0], bL[1]);
            mma_bf16(acc[2 * np],     aL, bH[0], bH[1]);
            mma_bf16(acc[2 * np + 1], aH, bH[2], bH[3]);
            mma_bf16(acc[2 * np + 1], aH, bL[2], bL[3]);
            mma_bf16(acc[2 * np + 1], aL, bH[2], bH[3]);
        }
    }

    // --- masked softmax (rows r0+g and r0+g+8) ---
    int rowA = r0 + g, rowB = rowA + 8;
    float mx0 = -3.0e38f, mx1 = -3.0e38f;
#pragma unroll
    for (int nt = 0; nt < 16; nt++) {
        float2 bv = *(const float2*)&bias[n0 + 8 * nt + 2 * t];
        acc[nt][0] += bv.x; acc[nt][1] += bv.y;
        acc[nt][2] += bv.x; acc[nt][3] += bv.y;
        mx0 = fmaxf(mx0, fmaxf(acc[nt][0], acc[nt][1]));
        mx1 = fmaxf(mx1, fmaxf(acc[nt][2], acc[nt][3]));
    }
    mx0 = fmaxf(mx0, __shfl_xor_sync(0xffffffffu, mx0, 1));
    mx0 = fmaxf(mx0, __shfl_xor_sync(0xffffffffu, mx0, 2));
    mx1 = fmaxf(mx1, __shfl_xor_sync(0xffffffffu, mx1, 1));
    mx1 = fmaxf(mx1, __shfl_xor_sync(0xffffffffu, mx1, 2));
    if (t == 0) {
        red[nw * 64 + rowA] = mx0;
        red[nw * 64 + rowB] = mx1;
    }
    __syncthreads();
    float M0 = fmaxf(red[rowA], red[64 + rowA]);
    float M1 = fmaxf(red[rowB], red[64 + rowB]);
    float s0 = 0.f, s1 = 0.f;
#pragma unroll
    for (int nt = 0; nt < 16; nt++) {
        float e0 = __expf(acc[nt][0] - M0);
        float e1 = __expf(acc[nt][1] - M0);
        float e2 = __expf(acc[nt][2] - M1);
        float e3 = __expf(acc[nt][3] - M1);
        acc[nt][0] = e0; acc[nt][1] = e1; acc[nt][2] = e2; acc[nt][3] = e3;
        s0 += e0 + e1; s1 += e2 + e3;
    }
    s0 += __shfl_xor_sync(0xffffffffu, s0, 1);
    s0 += __shfl_xor_sync(0xffffffffu, s0, 2);
    s1 += __shfl_xor_sync(0xffffffffu, s1, 1);
    s1 += __shfl_xor_sync(0xffffffffu, s1, 2);
    if (t == 0) {
        red[128 + nw * 64 + rowA] = s0;
        red[128 + nw * 64 + rowB] = s1;
    }
    __syncthreads();
    float inv0 = __fdividef(1.f, red[128 + rowA] + red[128 + 64 + rowA]);
    float inv1 = __fdividef(1.f, red[128 + rowB] + red[128 + 64 + rowB]);

    // --- write P split bf16 (overlays retired Q/K head; all warps past mma) ---
    {
        char* ph = smem + SM_PH;
        char* pl = smem + SM_PL;
#pragma unroll
        for (int nt = 0; nt < 16; nt++) {
            int col = n0 + 8 * nt + 2 * t;
            uint32_t h, lo;
            split_pack(acc[nt][0] * inv0, acc[nt][1] * inv0, h, lo);
            uint32_t offA = rowA * (ST_P * 2) + col * 2;
            *(uint32_t*)(ph + offA) = h;
            *(uint32_t*)(pl + offA) = lo;
            split_pack(acc[nt][2] * inv1, acc[nt][3] * inv1, h, lo);
            uint32_t offB = rowB * (ST_P * 2) + col * 2;
            *(uint32_t*)(ph + offB) = h;
            *(uint32_t*)(pl + offB) = lo;
        }
    }
    // --- convert V = M[b] (256 rows) split bf16 (overlays retired K tail) ---
    cvt_rows(Mb, smem + SM_VH, smem + SM_VL, tid, 256 * 64);
    __syncthreads();

    // --- PV GEMM: warp tile 16m x 64d, k = 256 (16 steps), 3 split terms ---
    int d0 = 64 * nw;
    float o[8][4];
#pragma unroll
    for (int i = 0; i < 8; i++)
#pragma unroll
        for (int j = 0; j < 4; j++) o[i][j] = 0.f;

    uint32_t vRowHalf = (uint32_t)(l & 15);
    uint32_t vColHalf = (uint32_t)((l >> 4) << 3);

#pragma unroll 1
    for (int ks = 0; ks < 16; ks++) {
        int k0 = 16 * ks;
        uint32_t aaddr = sbase + SM_PH + aRow * (ST_P * 2) + (k0 + aColHalf) * 2;
        uint32_t aH[4], aL[4];
        LDSM_X4(aH, aaddr);
        LDSM_X4(aL, aaddr + (SM_PL - SM_PH));
#pragma unroll
        for (int np = 0; np < 4; np++) {
            uint32_t baddr = sbase + SM_VH +
                (uint32_t)(k0 + vRowHalf) * (ST_K * 2) + (uint32_t)(d0 + 16 * np + vColHalf) * 2;
            uint32_t bH[4], bL[4];
            LDSM_X4T(bH, baddr);
            LDSM_X4T(bL, baddr + (SM_VL - SM_VH));
            mma_bf16(o[2 * np],     aH, bH[0], bH[1]);
            mma_bf16(o[2 * np],     aH, bL[0], bL[1]);
            mma_bf16(o[2 * np],     aL, bH[0], bH[1]);
            mma_bf16(o[2 * np + 1], aH, bH[2], bH[3]);
            mma_bf16(o[2 * np + 1], aH, bL[2], bL[3]);
            mma_bf16(o[2 * np + 1], aL, bH[2], bH[3]);
        }
    }

    // --- store output tile ---
    float* Ob = O + ((size_t)b * NN + i0) * DD;
#pragma unroll
    for (int nt = 0; nt < 8; nt++) {
        int col = d0 + 8 * nt + 2 * t;
        *(float2*)&Ob[(size_t)rowA * DD + col] = make_float2(o[nt][0], o[nt][1]);
        *(float2*)&Ob[(size_t)rowB * DD + col] = make_float2(o[nt][2], o[nt][3]);
    }
}

// ---------------------------------------------------------------------------
extern "C" void kernel_launch(void* const* d_in, const int* in_sizes, int n_in,
                              void* d_out, int out_size) {
    (void)in_sizes; (void)n_in; (void)out_size;
    const float* mirror    = (const float*)d_in[0];
    const float* satellite = (const float*)d_in[1];
    const void*  mask      = d_in[2];
    const float* Wq1 = (const float*)d_in[3];
    const float* Wk1 = (const float*)d_in[4];
    const float* Wq2 = (const float*)d_in[5];
    const float* Wk2 = (const float*)d_in[6];
    float* sat_out = (float*)d_out;
    float* mir_out = (float*)d_out + BND;

    const int smemG = (128 * 68 + 128 * 132) * 4;
    cudaFuncSetAttribute(gemm_nw_kernel, cudaFuncAttributeMaxDynamicSharedMemorySize, smemG);
    cudaFuncSetAttribute(attn_mma_kernel, cudaFuncAttributeMaxDynamicSharedMemorySize, SMEM_ATTN);

    detect_mask_kernel<<<1, 256>>>((const unsigned int*)mask);
    decode_mask_kernel<<<(BB * NN + 255) / 256, 256>>>(mask);

    prep_w_kernel<<<dim3(128, 2), 128>>>(Wq1, Wk1, Wq2, Wk2);
    gemm_nw_kernel<<<(BB * NN) / 64, 256, smemG>>>(mirror, 0);
    stage1_kernel<<<(BB * NN) / 8, 256>>>(mirror, satellite, sat_out);
    gemm_nw_kernel<<<(BB * NN) / 64, 256, smemG>>>(sat_out, 1);
    attn_mma_kernel<<<dim3(NN / 64, BB), 256, SMEM_ATTN>>>(mirror, mir_out);
}

// round 5
// speedup vs baseline: 2.0750x; 1.5274x over previous
#include <cuda_runtime.h>
#include <cuda_bf16.h>
#include <cstdint>

// Problem constants
#define BB 512
#define NN 256
#define DD 128
#define BND ((size_t)BB * NN * DD)

static __device__ float g_W1T[DD * DD];            // SCALE * (Wq1^T Wk1), [d][e]
static __device__ float g_W2T[DD * DD];
static __device__ __nv_bfloat16 g_W1h[DD * DD], g_W1l[DD * DD];
static __device__ __nv_bfloat16 g_W2h[DD * DD], g_W2l[DD * DD];
static __device__ float g_T[BND];                  // T = M @ W1 (fp32)
static __device__ __nv_bfloat16 g_Mh[BND], g_Ml[BND];   // mirror split
static __device__ __nv_bfloat16 g_Sh[BND], g_Sl[BND];   // sat_out split
static __device__ __nv_bfloat16 g_Kh[BND], g_Kl[BND];   // K2C split
static __device__ unsigned char g_mask[BB * NN];
static __device__ int g_mwidth1;

#define SCALE 0.08838834764831845f  // 1/sqrt(128)

// ============================ PTX helpers ==================================
__device__ __forceinline__ uint32_t smem_u32(const void* p) {
    uint32_t a;
    asm("{ .reg .u64 t; cvta.to.shared.u64 t, %1; cvt.u32.u64 %0, t; }" : "=r"(a) : "l"(p));
    return a;
}

#define LDSM_X4(r, a) \
    asm volatile("ldmatrix.sync.aligned.m8n8.x4.shared.b16 {%0,%1,%2,%3}, [%4];" \
        : "=r"((r)[0]), "=r"((r)[1]), "=r"((r)[2]), "=r"((r)[3]) : "r"(a))
#define LDSM_X4T(r, a) \
    asm volatile("ldmatrix.sync.aligned.m8n8.x4.trans.shared.b16 {%0,%1,%2,%3}, [%4];" \
        : "=r"((r)[0]), "=r"((r)[1]), "=r"((r)[2]), "=r"((r)[3]) : "r"(a))

__device__ __forceinline__ void mma_bf16(float* c, const uint32_t* a, uint32_t b0, uint32_t b1) {
    asm volatile(
        "mma.sync.aligned.m16n8k16.row.col.f32.bf16.bf16.f32 "
        "{%0,%1,%2,%3}, {%4,%5,%6,%7}, {%8,%9}, {%0,%1,%2,%3};"
        : "+f"(c[0]), "+f"(c[1]), "+f"(c[2]), "+f"(c[3])
        : "r"(a[0]), "r"(a[1]), "r"(a[2]), "r"(a[3]), "r"(b0), "r"(b1));
}

__device__ __forceinline__ void split_pack(float x, float y, uint32_t& h, uint32_t& l) {
    __nv_bfloat16 hx = __float2bfloat16(x);
    __nv_bfloat16 hy = __float2bfloat16(y);
    __nv_bfloat16 lx = __float2bfloat16(x - __bfloat162float(hx));
    __nv_bfloat16 ly = __float2bfloat16(y - __bfloat162float(hy));
    __nv_bfloat162 hh; hh.x = hx; hh.y = hy;
    __nv_bfloat162 ll; ll.x = lx; ll.y = ly;
    h = *(uint32_t*)&hh;
    l = *(uint32_t*)&ll;
}

// ======================= mask canonicalization =============================
__global__ void detect_mask_kernel(const unsigned int* __restrict__ m) {
    __shared__ int red[256];
    int tid = threadIdx.x;
    int p = 0;
    for (int i = tid; i < (BB * NN) / 4; i += 256) {
        unsigned int w = m[i];
        if (w != 0u && w != 1u && w != 0x3F800000u) p = 1;
    }
    red[tid] = p;
    __syncthreads();
    for (int s = 128; s > 0; s >>= 1) {
        if (tid < s) red[tid] |= red[tid + s];
        __syncthreads();
    }
    if (tid == 0) g_mwidth1 = red[0];
}

__global__ void decode_mask_kernel(const void* __restrict__ m) {
    int i = blockIdx.x * 256 + threadIdx.x;
    if (i >= BB * NN) return;
    unsigned char v;
    if (g_mwidth1) v = (((const unsigned char*)m)[i] != 0);
    else           v = (((const unsigned int*)m)[i] != 0u);
    g_mask[i] = v;
}

// ======================= weight contraction (scaled + split) ===============
__global__ void prep_w_kernel(const float* __restrict__ Wq1, const float* __restrict__ Wk1,
                              const float* __restrict__ Wq2, const float* __restrict__ Wk2) {
    int a = blockIdx.x, c = threadIdx.x;
    const float* X = (blockIdx.y == 0) ? Wq1 : Wq2;
    const float* Y = (blockIdx.y == 0) ? Wk1 : Wk2;
    float acc = 0.f;
#pragma unroll 8
    for (int k = 0; k < DD; k++)
        acc = fmaf(X[k * DD + c], Y[k * DD + a], acc);
    acc *= SCALE;
    __nv_bfloat16 h = __float2bfloat16(acc);
    __nv_bfloat16 l = __float2bfloat16(acc - __bfloat162float(h));
    int idx = a * DD + c;
    if (blockIdx.y == 0) {
        g_W1T[idx] = acc; g_W1h[idx] = h; g_W1l[idx] = l;
    } else {
        g_W2T[idx] = acc; g_W2h[idx] = h; g_W2l[idx] = l;
    }
}

// ======================= fp32 -> split bf16 (mirror) ========================
__global__ void split_kernel(const float* __restrict__ src) {
    size_t i = (size_t)blockIdx.x * 256 + threadIdx.x;
    if (i >= BND / 2) return;
    float2 v = ((const float2*)src)[i];
    uint32_t h, l;
    split_pack(v.x, v.y, h, l);
    ((uint32_t*)g_Mh)[i] = h;
    ((uint32_t*)g_Ml)[i] = l;
}

// ======================= projection GEMM (tensor, split bf16) ==============
// C[n,e] = sum_d A[n,d] W[d,e].  CTA: 128 rows x 128 cols.  8 warps: 4m x 2n,
// warp tile 32m x 64n.  asel: 0 = M split, 1 = S split.  wsel: 0 = W1, 1 = W2.
// omode: 0 -> write fp32 to g_T;  1 -> write split bf16 to g_Kh/g_Kl.
#define GT_ST   136                       // smem row stride in elems (272 B)
#define GT_AH   0
#define GT_AL   34816
#define GT_WH   69632
#define GT_WL   104448
#define GT_SMEM 139264

__global__ __launch_bounds__(256, 1)
void gemm_tc_kernel(int asel, int wsel, int omode) {
    extern __shared__ char smem[];
    uint32_t sbase = smem_u32(smem);
    int tid = threadIdx.x;
    int w = tid >> 5, l = tid & 31;
    size_t n0 = (size_t)blockIdx.x * 128;

    const __nv_bfloat16* Ah = asel ? g_Sh : g_Mh;
    const __nv_bfloat16* Al = asel ? g_Sl : g_Ml;
    const __nv_bfloat16* Wh = wsel ? g_W2h : g_W1h;
    const __nv_bfloat16* Wl = wsel ? g_W2l : g_W1l;

    // load A tile (128x128 bf16 hi/lo) and W (128x128 hi/lo)
    for (int idx = tid; idx < 2048; idx += 256) {
        int row = idx >> 4, c8 = idx & 15;
        *(uint4*)(smem + GT_AH + row * 272 + c8 * 16) =
            *(const uint4*)(Ah + (n0 + row) * DD + c8 * 8);
        *(uint4*)(smem + GT_AL + row * 272 + c8 * 16) =
            *(const uint4*)(Al + (n0 + row) * DD + c8 * 8);
        *(uint4*)(smem + GT_WH + row * 272 + c8 * 16) =
            *(const uint4*)(Wh + row * DD + c8 * 8);
        *(uint4*)(smem + GT_WL + row * 272 + c8 * 16) =
            *(const uint4*)(Wl + row * DD + c8 * 8);
    }
    __syncthreads();

    int mw = w & 3, nwp = w >> 2;
    int r0 = mw * 32, c0 = nwp * 64;
    float acc[2][8][4];
#pragma unroll
    for (int i = 0; i < 2; i++)
#pragma unroll
        for (int j = 0; j < 8; j++)
#pragma unroll
            for (int q = 0; q < 4; q++) acc[i][j][q] = 0.f;

    uint32_t aRowOff = (uint32_t)(l & 15);
    uint32_t halfOff = (uint32_t)((l >> 4) << 3);

#pragma unroll 1
    for (int ks = 0; ks < 8; ks++) {
        int k0 = 16 * ks;
        uint32_t aH0[4], aL0[4], aH1[4], aL1[4];
        uint32_t aaddr0 = sbase + GT_AH + (r0 + aRowOff) * 272 + (k0 + halfOff) * 2;
        LDSM_X4(aH0, aaddr0);
        LDSM_X4(aL0, aaddr0 + (GT_AL - GT_AH));
        uint32_t aaddr1 = aaddr0 + 16 * 272;
        LDSM_X4(aH1, aaddr1);
        LDSM_X4(aL1, aaddr1 + (GT_AL - GT_AH));
#pragma unroll
        for (int np = 0; np < 4; np++) {
            uint32_t baddr = sbase + GT_WH + (uint32_t)(k0 + (l & 15)) * 272 +
                             (uint32_t)(c0 + 16 * np + halfOff) * 2;
            uint32_t bH[4], bL[4];
            LDSM_X4T(bH, baddr);
            LDSM_X4T(bL, baddr + (GT_WL - GT_WH));
            mma_bf16(acc[0][2 * np],     aH0, bH[0], bH[1]);
            mma_bf16(acc[0][2 * np],     aH0, bL[0], bL[1]);
            mma_bf16(acc[0][2 * np],     aL0, bH[0], bH[1]);
            mma_bf16(acc[0][2 * np + 1], aH0, bH[2], bH[3]);
            mma_bf16(acc[0][2 * np + 1], aH0, bL[2], bL[3]);
            mma_bf16(acc[0][2 * np + 1], aL0, bH[2], bH[3]);
            mma_bf16(acc[1][2 * np],     aH1, bH[0], bH[1]);
            mma_bf16(acc[1][2 * np],     aH1, bL[0], bL[1]);
            mma_bf16(acc[1][2 * np],     aL1, bH[0], bH[1]);
            mma_bf16(acc[1][2 * np + 1], aH1, bH[2], bH[3]);
            mma_bf16(acc[1][2 * np + 1], aH1, bL[2], bL[3]);
            mma_bf16(acc[1][2 * np + 1], aL1, bH[2], bH[3]);
        }
    }

    int g = l >> 2, t = l & 3;
#pragma unroll
    for (int mt = 0; mt < 2; mt++) {
#pragma unroll
        for (int nt = 0; nt < 8; nt++) {
            size_t rowA = n0 + r0 + mt * 16 + g;
            size_t rowB = rowA + 8;
            int col = c0 + nt * 8 + 2 * t;
            if (omode == 0) {
                *(float2*)&g_T[rowA * DD + col] = make_float2(acc[mt][nt][0], acc[mt][nt][1]);
                *(float2*)&g_T[rowB * DD + col] = make_float2(acc[mt][nt][2], acc[mt][nt][3]);
            } else {
                uint32_t h, lo;
                split_pack(acc[mt][nt][0], acc[mt][nt][1], h, lo);
                *(uint32_t*)(g_Kh + rowA * DD + col) = h;
                *(uint32_t*)(g_Kl + rowA * DD + col) = lo;
                split_pack(acc[mt][nt][2], acc[mt][nt][3], h, lo);
                *(uint32_t*)(g_Kh + rowB * DD + col) = h;
                *(uint32_t*)(g_Kl + rowB * DD + col) = lo;
            }
        }
    }
}

// ======================= stage 1 (gate + sat_out + split) ==================
__global__ __launch_bounds__(256) void stage1_kernel(const float* __restrict__ M,
                                                     const float* __restrict__ S,
                                                     float* __restrict__ SO) {
    int w = threadIdx.x >> 5, l = threadIdx.x & 31;
    size_t n = (size_t)blockIdx.x * 8 + w;
    const float2* mrow = (const float2*)(M + n * DD);
    const float2* srow = (const float2*)(S + n * DD);
    const float2* trow = (const float2*)(g_T + n * DD);
    float2 sv[2];
    float p = 0.f;
#pragma unroll
    for (int k = 0; k < 2; k++) {
        int d2 = k * 32 + l;
        sv[k] = srow[d2];
        float2 tv = trow[d2];
        p = fmaf(sv[k].x, tv.x, p);
        p = fmaf(sv[k].y, tv.y, p);
    }
#pragma unroll
    for (int off = 16; off > 0; off >>= 1)
        p += __shfl_xor_sync(0xffffffffu, p, off);
    float alpha = p;  // SCALE folded into W1T
#pragma unroll
    for (int k = 0; k < 2; k++) {
        int d2 = k * 32 + l;
        float2 mv = mrow[d2];
        float2 o;
        o.x = fmaf(alpha, mv.x - sv[k].x, sv[k].x);
        o.y = fmaf(alpha, mv.y - sv[k].y, sv[k].y);
        ((float2*)(SO + n * DD))[d2] = o;
        uint32_t h, lo;
        split_pack(o.x, o.y, h, lo);
        ((uint32_t*)g_Sh)[n * 64 + d2] = h;
        ((uint32_t*)g_Sl)[n * 64 + d2] = lo;
    }
}

// ======================= mma.sync fused attention ==========================
// CTA = (batch b, i-tile of 64 rows). 256 threads = 8 warps, 4m x 2n grid.
#define ST_K   136      // elems (272 B rows)
#define ST_P   264      // elems (528 B rows)
#define SM_QH  0
#define SM_QL  17408
#define SM_KH  34816
#define SM_KL  104448
#define SM_PH  0
#define SM_PL  33792
#define SM_VH  67584
#define SM_VL  137216
#define SM_BIAS 206848
#define SM_RED  207872
#define SMEM_ATTN 208896

// copy precomputed split bf16 rows (global, row stride 128) into smem tiles
__device__ __forceinline__ void copy_rows(const __nv_bfloat16* __restrict__ sh,
                                          const __nv_bfloat16* __restrict__ sl,
                                          char* dh, char* dl, int tid, int rows) {
    for (int idx = tid; idx < rows * 16; idx += 256) {
        int row = idx >> 4, c8 = idx & 15;
        *(uint4*)(dh + row * (ST_K * 2) + c8 * 16) =
            *(const uint4*)(sh + (size_t)row * DD + c8 * 8);
        *(uint4*)(dl + row * (ST_K * 2) + c8 * 16) =
            *(const uint4*)(sl + (size_t)row * DD + c8 * 8);
    }
}

__global__ __launch_bounds__(256, 1)
void attn_mma_kernel(float* __restrict__ O) {
    extern __shared__ char smem[];
    uint32_t sbase = smem_u32(smem);

    int tid = threadIdx.x;
    int w = tid >> 5, l = tid & 31;
    int g = l >> 2, t = l & 3;
    int mw = w & 3, nw = w >> 2;
    int b = blockIdx.y;
    int i0 = blockIdx.x * 64;
    size_t boff = (size_t)b * NN * DD;

    float* bias = (float*)(smem + SM_BIAS);
    float* red = (float*)(smem + SM_RED);
    bias[tid] = g_mask[(size_t)b * NN + tid] ? 0.f : -1e30f;

    // --- stage split Q (64 rows of M) and K (256 rows of K2C) ---
    copy_rows(g_Mh + boff + (size_t)i0 * DD, g_Ml + boff + (size_t)i0 * DD,
              smem + SM_QH, smem + SM_QL, tid, 64);
    copy_rows(g_Kh + boff, g_Kl + boff, smem + SM_KH, smem + SM_KL, tid, 256);
    __syncthreads();

    // --- beta GEMM: warp tile 16m x 128n, k = 128 (8 steps), 3 split terms ---
    int r0 = 16 * mw;
    int n0 = 128 * nw;
    float acc[16][4];
#pragma unroll
    for (int i = 0; i < 16; i++)
#pragma unroll
        for (int j = 0; j < 4; j++) acc[i][j] = 0.f;

    uint32_t aRow = (uint32_t)(r0 + (l & 15));
    uint32_t aColHalf = (uint32_t)((l >> 4) << 3);
    uint32_t bRowBase = (uint32_t)(((l >> 4) << 3) + (l & 7));
    uint32_t bColHalf = (uint32_t)(((l >> 3) & 1) << 3);

#pragma unroll 1
    for (int ks = 0; ks < 8; ks++) {
        int k0 = 16 * ks;
        uint32_t aaddr = sbase + SM_QH + aRow * (ST_K * 2) + (k0 + aColHalf) * 2;
        uint32_t aH[4], aL[4];
        LDSM_X4(aH, aaddr);
        LDSM_X4(aL, aaddr + (SM_QL - SM_QH));
#pragma unroll
        for (int np = 0; np < 8; np++) {
            uint32_t baddr = sbase + SM_KH +
                (uint32_t)(n0 + 16 * np + bRowBase) * (ST_K * 2) + (k0 + bColHalf) * 2;
            uint32_t bH[4], bL[4];
            LDSM_X4(bH, baddr);
            LDSM_X4(bL, baddr + (SM_KL - SM_KH));
            mma_bf16(acc[2 * np],     aH, bH[0], bH[1]);
            mma_bf16(acc[2 * np],     aH, bL[0], bL[1]);
            mma_bf16(acc[2 * np],     aL, bH[0], bH[1]);
            mma_bf16(acc[2 * np + 1], aH, bH[2], bH[3]);
            mma_bf16(acc[2 * np + 1], aH, bL[2], bL[3]);
            mma_bf16(acc[2 * np + 1], aL, bH[2], bH[3]);
        }
    }

    // --- masked softmax (rows r0+g and r0+g+8) ---
    int rowA = r0 + g, rowB = rowA + 8;
    float mx0 = -3.0e38f, mx1 = -3.0e38f;
#pragma unroll
    for (int nt = 0; nt < 16; nt++) {
        float2 bv = *(const float2*)&bias[n0 + 8 * nt + 2 * t];
        acc[nt][0] += bv.x; acc[nt][1] += bv.y;
        acc[nt][2] += bv.x; acc[nt][3] += bv.y;
        mx0 = fmaxf(mx0, fmaxf(acc[nt][0], acc[nt][1]));
        mx1 = fmaxf(mx1, fmaxf(acc[nt][2], acc[nt][3]));
    }
    mx0 = fmaxf(mx0, __shfl_xor_sync(0xffffffffu, mx0, 1));
    mx0 = fmaxf(mx0, __shfl_xor_sync(0xffffffffu, mx0, 2));
    mx1 = fmaxf(mx1, __shfl_xor_sync(0xffffffffu, mx1, 1));
    mx1 = fmaxf(mx1, __shfl_xor_sync(0xffffffffu, mx1, 2));
    if (t == 0) {
        red[nw * 64 + rowA] = mx0;
        red[nw * 64 + rowB] = mx1;
    }
    __syncthreads();
    float M0 = fmaxf(red[rowA], red[64 + rowA]);
    float M1 = fmaxf(red[rowB], red[64 + rowB]);
    float s0 = 0.f, s1 = 0.f;
#pragma unroll
    for (int nt = 0; nt < 16; nt++) {
        float e0 = __expf(acc[nt][0] - M0);
        float e1 = __expf(acc[nt][1] - M0);
        float e2 = __expf(acc[nt][2] - M1);
        float e3 = __expf(acc[nt][3] - M1);
        acc[nt][0] = e0; acc[nt][1] = e1; acc[nt][2] = e2; acc[nt][3] = e3;
        s0 += e0 + e1; s1 += e2 + e3;
    }
    s0 += __shfl_xor_sync(0xffffffffu, s0, 1);
    s0 += __shfl_xor_sync(0xffffffffu, s0, 2);
    s1 += __shfl_xor_sync(0xffffffffu, s1, 1);
    s1 += __shfl_xor_sync(0xffffffffu, s1, 2);
    if (t == 0) {
        red[128 + nw * 64 + rowA] = s0;
        red[128 + nw * 64 + rowB] = s1;
    }
    __syncthreads();
    float inv0 = __fdividef(1.f, red[128 + rowA] + red[128 + 64 + rowA]);
    float inv1 = __fdividef(1.f, red[128 + rowB] + red[128 + 64 + rowB]);

    // --- write P split bf16 (overlays retired Q/K head) ---
    {
        char* ph = smem + SM_PH;
        char* pl = smem + SM_PL;
#pragma unroll
        for (int nt = 0; nt < 16; nt++) {
            int col = n0 + 8 * nt + 2 * t;
            uint32_t h, lo;
            split_pack(acc[nt][0] * inv0, acc[nt][1] * inv0, h, lo);
            uint32_t offA = rowA * (ST_P * 2) + col * 2;
            *(uint32_t*)(ph + offA) = h;
            *(uint32_t*)(pl + offA) = lo;
            split_pack(acc[nt][2] * inv1, acc[nt][3] * inv1, h, lo);
            uint32_t offB = rowB * (ST_P * 2) + col * 2;
            *(uint32_t*)(ph + offB) = h;
            *(uint32_t*)(pl + offB) = lo;
        }
    }
    // --- stage V = M[b] split (overlays retired K tail) ---
    copy_rows(g_Mh + boff, g_Ml + boff, smem + SM_VH, smem + SM_VL, tid, 256);
    __syncthreads();

    // --- PV GEMM: warp tile 16m x 64d, k = 256 (16 steps), 3 split terms ---
    int d0 = 64 * nw;
    float o[8][4];
#pragma unroll
    for (int i = 0; i < 8; i++)
#pragma unroll
        for (int j = 0; j < 4; j++) o[i][j] = 0.f;

    uint32_t vRowHalf = (uint32_t)(l & 15);
    uint32_t vColHalf = (uint32_t)((l >> 4) << 3);

#pragma unroll 1
    for (int ks = 0; ks < 16; ks++) {
        int k0 = 16 * ks;
        uint32_t aaddr = sbase + SM_PH + aRow * (ST_P * 2) + (k0 + aColHalf) * 2;
        uint32_t aH[4], aL[4];
        LDSM_X4(aH, aaddr);
        LDSM_X4(aL, aaddr + (SM_PL - SM_PH));
#pragma unroll
        for (int np = 0; np < 4; np++) {
            uint32_t baddr = sbase + SM_VH +
                (uint32_t)(k0 + vRowHalf) * (ST_K * 2) + (uint32_t)(d0 + 16 * np + vColHalf) * 2;
            uint32_t bH[4], bL[4];
            LDSM_X4T(bH, baddr);
            LDSM_X4T(bL, baddr + (SM_VL - SM_VH));
            mma_bf16(o[2 * np],     aH, bH[0], bH[1]);
            mma_bf16(o[2 * np],     aH, bL[0], bL[1]);
            mma_bf16(o[2 * np],     aL, bH[0], bH[1]);
            mma_bf16(o[2 * np + 1], aH, bH[2], bH[3]);
            mma_bf16(o[2 * np + 1], aH, bL[2], bL[3]);
            mma_bf16(o[2 * np + 1], aL, bH[2], bH[3]);
        }
    }

    // --- store output tile ---
    float* Ob = O + ((size_t)b * NN + i0) * DD;
#pragma unroll
    for (int nt = 0; nt < 8; nt++) {
        int col = d0 + 8 * nt + 2 * t;
        *(float2*)&Ob[(size_t)rowA * DD + col] = make_float2(o[nt][0], o[nt][1]);
        *(float2*)&Ob[(size_t)rowB * DD + col] = make_float2(o[nt][2], o[nt][3]);
    }
}

// ---------------------------------------------------------------------------
extern "C" void kernel_launch(void* const* d_in, const int* in_sizes, int n_in,
                              void* d_out, int out_size) {
    (void)in_sizes; (void)n_in; (void)out_size;
    const float* mirror    = (const float*)d_in[0];
    const float* satellite = (const float*)d_in[1];
    const void*  mask      = d_in[2];
    const float* Wq1 = (const float*)d_in[3];
    const float* Wk1 = (const float*)d_in[4];
    const float* Wq2 = (const float*)d_in[5];
    const float* Wk2 = (const float*)d_in[6];
    float* sat_out = (float*)d_out;
    float* mir_out = (float*)d_out + BND;

    cudaFuncSetAttribute(gemm_tc_kernel, cudaFuncAttributeMaxDynamicSharedMemorySize, GT_SMEM);
    cudaFuncSetAttribute(attn_mma_kernel, cudaFuncAttributeMaxDynamicSharedMemorySize, SMEM_ATTN);

    detect_mask_kernel<<<1, 256>>>((const unsigned int*)mask);
    decode_mask_kernel<<<(BB * NN + 255) / 256, 256>>>(mask);

    prep_w_kernel<<<dim3(128, 2), 128>>>(Wq1, Wk1, Wq2, Wk2);
    split_kernel<<<(int)((BND / 2 + 255) / 256), 256>>>(mirror);

    // T = M @ W1  (fp32 out)
    gemm_tc_kernel<<<(BB * NN) / 128, 256, GT_SMEM>>>(0, 0, 0);
    // alpha, sat_out (+ split)
    stage1_kernel<<<(BB * NN) / 8, 256>>>(mirror, satellite, sat_out);
    // K2C = sat_out @ W2  (split bf16 out)
    gemm_tc_kernel<<<(BB * NN) / 128, 256, GT_SMEM>>>(1, 1, 1);
    // fused masked attention
    attn_mma_kernel<<<dim3(NN / 64, BB), 256, SMEM_ATTN>>>(mir_out);
}

// round 6
// speedup vs baseline: 3.1417x; 1.5141x over previous
#include <cuda_runtime.h>
#include <cuda_fp16.h>
#include <cstdint>

// Problem constants
#define BB 512
#define NN 256
#define DD 128
#define BND ((size_t)BB * NN * DD)

static __device__ __half g_W1h[DD * DD], g_W1l[DD * DD];
static __device__ __half g_W2h[DD * DD], g_W2l[DD * DD];
static __device__ float g_T[BND];                    // T = M @ W1 (fp32)
static __device__ __half g_Mh[BND], g_Ml[BND];       // mirror split
static __device__ __half g_Sh[BND], g_Sl[BND];       // sat_out split
static __device__ __half g_Kh[BND], g_Kl[BND];       // K2C split (COMPACT rows)
static __device__ unsigned char g_mask[BB * NN];
static __device__ int g_idx[BB * NN];                // compact pos -> j
static __device__ int g_nv[BB];                      // valid count per batch
static __device__ int g_mwidth1;

#define SCALE 0.08838834764831845f  // 1/sqrt(128)

// ============================ PTX helpers ==================================
__device__ __forceinline__ uint32_t smem_u32(const void* p) {
    uint32_t a;
    asm("{ .reg .u64 t; cvta.to.shared.u64 t, %1; cvt.u32.u64 %0, t; }" : "=r"(a) : "l"(p));
    return a;
}

#define LDSM_X4(r, a) \
    asm volatile("ldmatrix.sync.aligned.m8n8.x4.shared.b16 {%0,%1,%2,%3}, [%4];" \
        : "=r"((r)[0]), "=r"((r)[1]), "=r"((r)[2]), "=r"((r)[3]) : "r"(a))
#define LDSM_X4T(r, a) \
    asm volatile("ldmatrix.sync.aligned.m8n8.x4.trans.shared.b16 {%0,%1,%2,%3}, [%4];" \
        : "=r"((r)[0]), "=r"((r)[1]), "=r"((r)[2]), "=r"((r)[3]) : "r"(a))

__device__ __forceinline__ void mma_fp16(float* c, const uint32_t* a, uint32_t b0, uint32_t b1) {
    asm volatile(
        "mma.sync.aligned.m16n8k16.row.col.f32.f16.f16.f32 "
        "{%0,%1,%2,%3}, {%4,%5,%6,%7}, {%8,%9}, {%0,%1,%2,%3};"
        : "+f"(c[0]), "+f"(c[1]), "+f"(c[2]), "+f"(c[3])
        : "r"(a[0]), "r"(a[1]), "r"(a[2]), "r"(a[3]), "r"(b0), "r"(b1));
}

__device__ __forceinline__ void split_pack(float x, float y, uint32_t& h, uint32_t& l) {
    __half hx = __float2half(x);
    __half hy = __float2half(y);
    __half lx = __float2half(x - __half2float(hx));
    __half ly = __float2half(y - __half2float(hy));
    __half2 hh; hh.x = hx; hh.y = hy;
    __half2 ll; ll.x = lx; ll.y = ly;
    h = *(uint32_t*)&hh;
    l = *(uint32_t*)&ll;
}

// ======================= mask canonicalization =============================
__global__ void detect_mask_kernel(const unsigned int* __restrict__ m) {
    __shared__ int red[256];
    int tid = threadIdx.x;
    int p = 0;
    for (int i = tid; i < (BB * NN) / 4; i += 256) {
        unsigned int w = m[i];
        if (w != 0u && w != 1u && w != 0x3F800000u) p = 1;
    }
    red[tid] = p;
    __syncthreads();
    for (int s = 128; s > 0; s >>= 1) {
        if (tid < s) red[tid] |= red[tid + s];
        __syncthreads();
    }
    if (tid == 0) g_mwidth1 = red[0];
}

__global__ void decode_mask_kernel(const void* __restrict__ m) {
    int i = blockIdx.x * 256 + threadIdx.x;
    if (i >= BB * NN) return;
    unsigned char v;
    if (g_mwidth1) v = (((const unsigned char*)m)[i] != 0);
    else           v = (((const unsigned int*)m)[i] != 0u);
    g_mask[i] = v;
}

// ======================= per-batch valid-key compaction ====================
__global__ void compact_kernel() {
    int b = blockIdx.x;
    int tid = threadIdx.x;
    int w = tid >> 5, l = tid & 31;
    __shared__ int wcnt[8], woff[8];
    int valid = g_mask[b * NN + tid] ? 1 : 0;
    unsigned bal = __ballot_sync(0xffffffffu, valid);
    int pre = __popc(bal & ((1u << l) - 1u));
    if (l == 31) wcnt[w] = __popc(bal);
    g_idx[b * NN + tid] = 0;   // prefill pads with a safe (valid) index
    __syncthreads();
    if (tid == 0) {
        int s = 0;
        for (int i = 0; i < 8; i++) { woff[i] = s; s += wcnt[i]; }
        g_nv[b] = s;
    }
    __syncthreads();
    if (valid) g_idx[b * NN + woff[w] + pre] = tid;
}

// ======================= weight contraction (scaled + split) ===============
__global__ void prep_w_kernel(const float* __restrict__ Wq1, const float* __restrict__ Wk1,
                              const float* __restrict__ Wq2, const float* __restrict__ Wk2) {
    int a = blockIdx.x, c = threadIdx.x;
    const float* X = (blockIdx.y == 0) ? Wq1 : Wq2;
    const float* Y = (blockIdx.y == 0) ? Wk1 : Wk2;
    float acc = 0.f;
#pragma unroll 8
    for (int k = 0; k < DD; k++)
        acc = fmaf(X[k * DD + c], Y[k * DD + a], acc);
    acc *= SCALE;
    __half h = __float2half(acc);
    __half l = __float2half(acc - __half2float(h));
    int idx = a * DD + c;
    if (blockIdx.y == 0) { g_W1h[idx] = h; g_W1l[idx] = l; }
    else                 { g_W2h[idx] = h; g_W2l[idx] = l; }
}

// ======================= fp32 -> split fp16 (mirror) ========================
__global__ void split_kernel(const float* __restrict__ src) {
    size_t i = (size_t)blockIdx.x * 256 + threadIdx.x;
    if (i >= BND / 2) return;
    float2 v = ((const float2*)src)[i];
    uint32_t h, l;
    split_pack(v.x, v.y, h, l);
    ((uint32_t*)g_Mh)[i] = h;
    ((uint32_t*)g_Ml)[i] = l;
}

// ======================= T GEMM (2-term fp16 tensor) ========================
// T[n,e] = sum_d M[n,d] W1[d,e], drops Ml*W term.  128x128 tile, 8 warps 4mx2n.
#define GT_A   0
#define GT_WH  34816
#define GT_WL  69632
#define GT_SMEM 104448

__global__ __launch_bounds__(256, 1)
void gemm_T_kernel() {
    extern __shared__ char smem[];
    uint32_t sbase = smem_u32(smem);
    int tid = threadIdx.x;
    int w = tid >> 5, l = tid & 31;
    size_t n0 = (size_t)blockIdx.x * 128;

    for (int idx = tid; idx < 2048; idx += 256) {
        int row = idx >> 4, c8 = idx & 15;
        *(uint4*)(smem + GT_A + row * 272 + c8 * 16) =
            *(const uint4*)(g_Mh + (n0 + row) * DD + c8 * 8);
        *(uint4*)(smem + GT_WH + row * 272 + c8 * 16) =
            *(const uint4*)(g_W1h + row * DD + c8 * 8);
        *(uint4*)(smem + GT_WL + row * 272 + c8 * 16) =
            *(const uint4*)(g_W1l + row * DD + c8 * 8);
    }
    __syncthreads();

    int mw = w & 3, nwp = w >> 2;
    int r0 = mw * 32, c0 = nwp * 64;
    float acc[2][8][4];
#pragma unroll
    for (int i = 0; i < 2; i++)
#pragma unroll
        for (int j = 0; j < 8; j++)
#pragma unroll
            for (int q = 0; q < 4; q++) acc[i][j][q] = 0.f;

    uint32_t halfOff = (uint32_t)((l >> 4) << 3);
#pragma unroll 1
    for (int ks = 0; ks < 8; ks++) {
        int k0 = 16 * ks;
        uint32_t aH0[4], aH1[4];
        uint32_t aaddr0 = sbase + GT_A + (r0 + (l & 15)) * 272 + (k0 + halfOff) * 2;
        LDSM_X4(aH0, aaddr0);
        LDSM_X4(aH1, aaddr0 + 16 * 272);
#pragma unroll
        for (int np = 0; np < 4; np++) {
            uint32_t baddr = sbase + GT_WH + (uint32_t)(k0 + (l & 15)) * 272 +
                             (uint32_t)(c0 + 16 * np + halfOff) * 2;
            uint32_t bH[4], bL[4];
            LDSM_X4T(bH, baddr);
            LDSM_X4T(bL, baddr + (GT_WL - GT_WH));
            mma_fp16(acc[0][2 * np],     aH0, bH[0], bH[1]);
            mma_fp16(acc[0][2 * np],     aH0, bL[0], bL[1]);
            mma_fp16(acc[0][2 * np + 1], aH0, bH[2], bH[3]);
            mma_fp16(acc[0][2 * np + 1], aH0, bL[2], bL[3]);
            mma_fp16(acc[1][2 * np],     aH1, bH[0], bH[1]);
            mma_fp16(acc[1][2 * np],     aH1, bL[0], bL[1]);
            mma_fp16(acc[1][2 * np + 1], aH1, bH[2], bH[3]);
            mma_fp16(acc[1][2 * np + 1], aH1, bL[2], bL[3]);
        }
    }

    int g = l >> 2, t = l & 3;
#pragma unroll
    for (int mt = 0; mt < 2; mt++)
#pragma unroll
        for (int nt = 0; nt < 8; nt++) {
            size_t rowA = n0 + r0 + mt * 16 + g;
            size_t rowB = rowA + 8;
            int col = c0 + nt * 8 + 2 * t;
            *(float2*)&g_T[rowA * DD + col] = make_float2(acc[mt][nt][0], acc[mt][nt][1]);
            *(float2*)&g_T[rowB * DD + col] = make_float2(acc[mt][nt][2], acc[mt][nt][3]);
        }
}

// ======================= K2C GEMM (3-term, gathered, compact out) ==========
#define GK_AH  0
#define GK_AL  34816
#define GK_WH  69632
#define GK_WL  104448
#define GK_SMEM 139264

__global__ __launch_bounds__(256, 1)
void gemm_K2C_kernel() {
    int b = blockIdx.x >> 1;
    int pos0 = (blockIdx.x & 1) * 128;
    if (pos0 >= g_nv[b]) return;   // whole tile is padding
    extern __shared__ char smem[];
    uint32_t sbase = smem_u32(smem);
    int tid = threadIdx.x;
    int w = tid >> 5, l = tid & 31;

    for (int idx = tid; idx < 2048; idx += 256) {
        int row = idx >> 4, c8 = idx & 15;
        int j = g_idx[b * NN + pos0 + row];
        size_t srow = ((size_t)b * NN + j) * DD;
        *(uint4*)(smem + GK_AH + row * 272 + c8 * 16) = *(const uint4*)(g_Sh + srow + c8 * 8);
        *(uint4*)(smem + GK_AL + row * 272 + c8 * 16) = *(const uint4*)(g_Sl + srow + c8 * 8);
        *(uint4*)(smem + GK_WH + row * 272 + c8 * 16) = *(const uint4*)(g_W2h + row * DD + c8 * 8);
        *(uint4*)(smem + GK_WL + row * 272 + c8 * 16) = *(const uint4*)(g_W2l + row * DD + c8 * 8);
    }
    __syncthreads();

    int mw = w & 3, nwp = w >> 2;
    int r0 = mw * 32, c0 = nwp * 64;
    float acc[2][8][4];
#pragma unroll
    for (int i = 0; i < 2; i++)
#pragma unroll
        for (int j = 0; j < 8; j++)
#pragma unroll
            for (int q = 0; q < 4; q++) acc[i][j][q] = 0.f;

    uint32_t halfOff = (uint32_t)((l >> 4) << 3);
#pragma unroll 1
    for (int ks = 0; ks < 8; ks++) {
        int k0 = 16 * ks;
        uint32_t aH0[4], aL0[4], aH1[4], aL1[4];
        uint32_t aaddr0 = sbase + GK_AH + (r0 + (l & 15)) * 272 + (k0 + halfOff) * 2;
        LDSM_X4(aH0, aaddr0);
        LDSM_X4(aL0, aaddr0 + (GK_AL - GK_AH));
        LDSM_X4(aH1, aaddr0 + 16 * 272);
        LDSM_X4(aL1, aaddr0 + 16 * 272 + (GK_AL - GK_AH));
#pragma unroll
        for (int np = 0; np < 4; np++) {
            uint32_t baddr = sbase + GK_WH + (uint32_t)(k0 + (l & 15)) * 272 +
                             (uint32_t)(c0 + 16 * np + halfOff) * 2;
            uint32_t bH[4], bL[4];
            LDSM_X4T(bH, baddr);
            LDSM_X4T(bL, baddr + (GK_WL - GK_WH));
            mma_fp16(acc[0][2 * np],     aH0, bH[0], bH[1]);
            mma_fp16(acc[0][2 * np],     aH0, bL[0], bL[1]);
            mma_fp16(acc[0][2 * np],     aL0, bH[0], bH[1]);
            mma_fp16(acc[0][2 * np + 1], aH0, bH[2], bH[3]);
            mma_fp16(acc[0][2 * np + 1], aH0, bL[2], bL[3]);
            mma_fp16(acc[0][2 * np + 1], aL0, bH[2], bH[3]);
            mma_fp16(acc[1][2 * np],     aH1, bH[0], bH[1]);
            mma_fp16(acc[1][2 * np],     aH1, bL[0], bL[1]);
            mma_fp16(acc[1][2 * np],     aL1, bH[0], bH[1]);
            mma_fp16(acc[1][2 * np + 1], aH1, bH[2], bH[3]);
            mma_fp16(acc[1][2 * np + 1], aH1, bL[2], bL[3]);
            mma_fp16(acc[1][2 * np + 1], aL1, bH[2], bH[3]);
        }
    }

    int g = l >> 2, t = l & 3;
#pragma unroll
    for (int mt = 0; mt < 2; mt++)
#pragma unroll
        for (int nt = 0; nt < 8; nt++) {
            size_t rowA = (size_t)b * NN + pos0 + r0 + mt * 16 + g;
            size_t rowB = rowA + 8;
            int col = c0 + nt * 8 + 2 * t;
            uint32_t h, lo;
            split_pack(acc[mt][nt][0], acc[mt][nt][1], h, lo);
            *(uint32_t*)(g_Kh + rowA * DD + col) = h;
            *(uint32_t*)(g_Kl + rowA * DD + col) = lo;
            split_pack(acc[mt][nt][2], acc[mt][nt][3], h, lo);
            *(uint32_t*)(g_Kh + rowB * DD + col) = h;
            *(uint32_t*)(g_Kl + rowB * DD + col) = lo;
        }
}

// ======================= stage 1 (gate + sat_out + split) ==================
__global__ __launch_bounds__(256) void stage1_kernel(const float* __restrict__ M,
                                                     const float* __restrict__ S,
                                                     float* __restrict__ SO) {
    int w = threadIdx.x >> 5, l = threadIdx.x & 31;
    size_t n = (size_t)blockIdx.x * 8 + w;
    const float2* mrow = (const float2*)(M + n * DD);
    const float2* srow = (const float2*)(S + n * DD);
    const float2* trow = (const float2*)(g_T + n * DD);
    float2 sv[2];
    float p = 0.f;
#pragma unroll
    for (int k = 0; k < 2; k++) {
        int d2 = k * 32 + l;
        sv[k] = srow[d2];
        float2 tv = trow[d2];
        p = fmaf(sv[k].x, tv.x, p);
        p = fmaf(sv[k].y, tv.y, p);
    }
#pragma unroll
    for (int off = 16; off > 0; off >>= 1)
        p += __shfl_xor_sync(0xffffffffu, p, off);
    float alpha = p;  // SCALE folded into W1
#pragma unroll
    for (int k = 0; k < 2; k++) {
        int d2 = k * 32 + l;
        float2 mv = mrow[d2];
        float2 o;
        o.x = fmaf(alpha, mv.x - sv[k].x, sv[k].x);
        o.y = fmaf(alpha, mv.y - sv[k].y, sv[k].y);
        ((float2*)(SO + n * DD))[d2] = o;
        uint32_t h, lo;
        split_pack(o.x, o.y, h, lo);
        ((uint32_t*)g_Sh)[n * 64 + d2] = h;
        ((uint32_t*)g_Sl)[n * 64 + d2] = lo;
    }
}

// ======================= fused attention (compacted keys) ==================
// CTA = (batch b, i-tile of 64 rows). 8 warps: 4m x 2n.
#define SM_QH  0
#define SM_QL  17408
#define SM_KH  34816
#define SM_KL  104448
#define SM_PH  0         // P (hi only, stride 528B) overlays Q
#define SM_VH  34816     // V overlays K
#define SM_VL  104448
#define SMEM_ATTN 174080

#define BETA_CHUNK(ACC, CBASE) do {                                                 \
    _Pragma("unroll")                                                               \
    for (int ks = 0; ks < 8; ks++) {                                                \
        int k0 = 16 * ks;                                                           \
        uint32_t aH[4], aL[4];                                                      \
        uint32_t aaddr = sbase + SM_QH + aRow * 272 + (k0 + halfOff) * 2;           \
        LDSM_X4(aH, aaddr);                                                         \
        LDSM_X4(aL, aaddr + (SM_QL - SM_QH));                                       \
        _Pragma("unroll")                                                           \
        for (int np = 0; np < 4; np++) {                                            \
            uint32_t baddr = sbase + SM_KH +                                        \
                (uint32_t)((CBASE) + nw * 64 + 16 * np + bRowBase) * 272 +          \
                (k0 + bColHalf) * 2;                                                \
            uint32_t bH[4], bL[4];                                                  \
            LDSM_X4(bH, baddr);                                                     \
            LDSM_X4(bL, baddr + (SM_KL - SM_KH));                                   \
            mma_fp16(ACC[2 * np],     aH, bH[0], bH[1]);                            \
            mma_fp16(ACC[2 * np],     aH, bL[0], bL[1]);                            \
            mma_fp16(ACC[2 * np],     aL, bH[0], bH[1]);                            \
            mma_fp16(ACC[2 * np + 1], aH, bH[2], bH[3]);                            \
            mma_fp16(ACC[2 * np + 1], aH, bL[2], bL[3]);                            \
            mma_fp16(ACC[2 * np + 1], aL, bH[2], bH[3]);                            \
        }                                                                           \
    }                                                                               \
} while (0)

__global__ __launch_bounds__(256, 1)
void attn_kernel(float* __restrict__ O) {
    extern __shared__ char smem[];
    __shared__ float s_bias[256];
    __shared__ float s_red[256];
    __shared__ int s_idx[256];
    uint32_t sbase = smem_u32(smem);

    int tid = threadIdx.x;
    int w = tid >> 5, l = tid & 31;
    int g = l >> 2, t = l & 3;
    int mw = w & 3, nw = w >> 2;
    int b = blockIdx.y;
    int i0 = blockIdx.x * 64;
    size_t boff = (size_t)b * NN * DD;

    int nv = g_nv[b];
    int ncols = (nv > 128) ? 256 : 128;
    int kpad = (nv + 15) & ~15;

    s_idx[tid] = g_idx[b * NN + tid];
    s_bias[tid] = (tid < nv) ? 0.f : -1e30f;

    // stage Q (64 rows of M split)
    for (int idx = tid; idx < 64 * 16; idx += 256) {
        int row = idx >> 4, c8 = idx & 15;
        size_t src = boff + (size_t)(i0 + row) * DD + c8 * 8;
        *(uint4*)(smem + SM_QH + row * 272 + c8 * 16) = *(const uint4*)(g_Mh + src);
        *(uint4*)(smem + SM_QL + row * 272 + c8 * 16) = *(const uint4*)(g_Ml + src);
    }
    // stage K compact (zero pads)
    {
        uint4 z = make_uint4(0, 0, 0, 0);
        for (int idx = tid; idx < ncols * 16; idx += 256) {
            int row = idx >> 4, c8 = idx & 15;
            uint4 vh = z, vl = z;
            if (row < nv) {
                size_t src = boff + (size_t)row * DD + c8 * 8;
                vh = *(const uint4*)(g_Kh + src);
                vl = *(const uint4*)(g_Kl + src);
            }
            *(uint4*)(smem + SM_KH + row * 272 + c8 * 16) = vh;
            *(uint4*)(smem + SM_KL + row * 272 + c8 * 16) = vl;
        }
    }
    __syncthreads();

    // --- beta GEMM over valid chunks ---
    uint32_t aRow = (uint32_t)(16 * mw + (l & 15));
    uint32_t halfOff = (uint32_t)((l >> 4) << 3);
    uint32_t bRowBase = (uint32_t)(((l >> 4) << 3) + (l & 7));
    uint32_t bColHalf = (uint32_t)(((l >> 3) & 1) << 3);

    float acc0[8][4], acc1[8][4];
#pragma unroll
    for (int j = 0; j < 8; j++)
#pragma unroll
        for (int q = 0; q < 4; q++) { acc0[j][q] = 0.f; acc1[j][q] = 0.f; }

    BETA_CHUNK(acc0, 0);
    if (ncols > 128) BETA_CHUNK(acc1, 128);

    // --- masked softmax (rows rowA, rowB) ---
    int rowA = 16 * mw + g, rowB = rowA + 8;
    float mx0 = -3.0e38f, mx1 = -3.0e38f;
#pragma unroll
    for (int j = 0; j < 8; j++) {
        float2 bv = *(const float2*)&s_bias[nw * 64 + j * 8 + 2 * t];
        acc0[j][0] += bv.x; acc0[j][1] += bv.y;
        acc0[j][2] += bv.x; acc0[j][3] += bv.y;
        mx0 = fmaxf(mx0, fmaxf(acc0[j][0], acc0[j][1]));
        mx1 = fmaxf(mx1, fmaxf(acc0[j][2], acc0[j][3]));
    }
    if (ncols > 128) {
#pragma unroll
        for (int j = 0; j < 8; j++) {
            float2 bv = *(const float2*)&s_bias[128 + nw * 64 + j * 8 + 2 * t];
            acc1[j][0] += bv.x; acc1[j][1] += bv.y;
            acc1[j][2] += bv.x; acc1[j][3] += bv.y;
            mx0 = fmaxf(mx0, fmaxf(acc1[j][0], acc1[j][1]));
            mx1 = fmaxf(mx1, fmaxf(acc1[j][2], acc1[j][3]));
        }
    }
    mx0 = fmaxf(mx0, __shfl_xor_sync(0xffffffffu, mx0, 1));
    mx0 = fmaxf(mx0, __shfl_xor_sync(0xffffffffu, mx0, 2));
    mx1 = fmaxf(mx1, __shfl_xor_sync(0xffffffffu, mx1, 1));
    mx1 = fmaxf(mx1, __shfl_xor_sync(0xffffffffu, mx1, 2));
    if (t == 0) {
        s_red[nw * 64 + rowA] = mx0;
        s_red[nw * 64 + rowB] = mx1;
    }
    __syncthreads();
    float M0 = fmaxf(s_red[rowA], s_red[64 + rowA]);
    float M1 = fmaxf(s_red[rowB], s_red[64 + rowB]);
    float s0 = 0.f, s1 = 0.f;
#pragma unroll
    for (int j = 0; j < 8; j++) {
        acc0[j][0] = __expf(acc0[j][0] - M0); s0 += acc0[j][0];
        acc0[j][1] = __expf(acc0[j][1] - M0); s0 += acc0[j][1];
        acc0[j][2] = __expf(acc0[j][2] - M1); s1 += acc0[j][2];
        acc0[j][3] = __expf(acc0[j][3] - M1); s1 += acc0[j][3];
    }
    if (ncols > 128) {
#pragma unroll
        for (int j = 0; j < 8; j++) {
            acc1[j][0] = __expf(acc1[j][0] - M0); s0 += acc1[j][0];
            acc1[j][1] = __expf(acc1[j][1] - M0); s0 += acc1[j][1];
            acc1[j][2] = __expf(acc1[j][2] - M1); s1 += acc1[j][2];
            acc1[j][3] = __expf(acc1[j][3] - M1); s1 += acc1[j][3];
        }
    }
    s0 += __shfl_xor_sync(0xffffffffu, s0, 1);
    s0 += __shfl_xor_sync(0xffffffffu, s0, 2);
    s1 += __shfl_xor_sync(0xffffffffu, s1, 1);
    s1 += __shfl_xor_sync(0xffffffffu, s1, 2);
    __syncthreads();   // everyone done with s_red round 1
    if (t == 0) {
        s_red[128 + nw * 64 + rowA] = s0;
        s_red[128 + nw * 64 + rowB] = s1;
    }
    __syncthreads();
    float inv0 = __fdividef(1.f, s_red[128 + rowA] + s_red[128 + 64 + rowA]);
    float inv1 = __fdividef(1.f, s_red[128 + rowB] + s_red[128 + 64 + rowB]);

    // --- write P (fp16 hi only) over retired Q region ---
    {
        char* ph = smem + SM_PH;
#pragma unroll
        for (int j = 0; j < 8; j++) {
            int col = nw * 64 + j * 8 + 2 * t;
            __half2 a; a.x = __float2half(acc0[j][0] * inv0); a.y = __float2half(acc0[j][1] * inv0);
            *(uint32_t*)(ph + rowA * 528 + col * 2) = *(uint32_t*)&a;
            __half2 c; c.x = __float2half(acc0[j][2] * inv1); c.y = __float2half(acc0[j][3] * inv1);
            *(uint32_t*)(ph + rowB * 528 + col * 2) = *(uint32_t*)&c;
        }
        if (ncols > 128) {
#pragma unroll
            for (int j = 0; j < 8; j++) {
                int col = 128 + nw * 64 + j * 8 + 2 * t;
                __half2 a; a.x = __float2half(acc1[j][0] * inv0); a.y = __float2half(acc1[j][1] * inv0);
                *(uint32_t*)(ph + rowA * 528 + col * 2) = *(uint32_t*)&a;
                __half2 c; c.x = __float2half(acc1[j][2] * inv1); c.y = __float2half(acc1[j][3] * inv1);
                *(uint32_t*)(ph + rowB * 528 + col * 2) = *(uint32_t*)&c;
            }
        }
    }
    // --- stage V gathered (overlays retired K) ---
    {
        uint4 z = make_uint4(0, 0, 0, 0);
        for (int idx = tid; idx < kpad * 16; idx += 256) {
            int row = idx >> 4, c8 = idx & 15;
            uint4 vh = z, vl = z;
            if (row < nv) {
                size_t src = boff + (size_t)s_idx[row] * DD + c8 * 8;
                vh = *(const uint4*)(g_Mh + src);
                vl = *(const uint4*)(g_Ml + src);
            }
            *(uint4*)(smem + SM_VH + row * 272 + c8 * 16) = vh;
            *(uint4*)(smem + SM_VL + row * 272 + c8 * 16) = vl;
        }
    }
    __syncthreads();

    // --- PV GEMM: 2-term (P hi * (Vh + Vl)), k up to kpad ---
    int d0 = 64 * nw;
    float o[8][4];
#pragma unroll
    for (int i = 0; i < 8; i++)
#pragma unroll
        for (int j = 0; j < 4; j++) o[i][j] = 0.f;

    int ksteps = kpad >> 4;
#pragma unroll 1
    for (int ks = 0; ks < ksteps; ks++) {
        int k0 = 16 * ks;
        uint32_t aH[4];
        LDSM_X4(aH, sbase + SM_PH + aRow * 528 + (k0 + halfOff) * 2);
#pragma unroll
        for (int np = 0; np < 4; np++) {
            uint32_t baddr = sbase + SM_VH + (uint32_t)(k0 + (l & 15)) * 272 +
                             (uint32_t)(d0 + 16 * np + halfOff) * 2;
            uint32_t bH[4], bL[4];
            LDSM_X4T(bH, baddr);
            LDSM_X4T(bL, baddr + (SM_VL - SM_VH));
            mma_fp16(o[2 * np],     aH, bH[0], bH[1]);
            mma_fp16(o[2 * np],     aH, bL[0], bL[1]);
            mma_fp16(o[2 * np + 1], aH, bH[2], bH[3]);
            mma_fp16(o[2 * np + 1], aH, bL[2], bL[3]);
        }
    }

    float* Ob = O + ((size_t)b * NN + i0) * DD;
#pragma unroll
    for (int nt = 0; nt < 8; nt++) {
        int col = d0 + 8 * nt + 2 * t;
        *(float2*)&Ob[(size_t)rowA * DD + col] = make_float2(o[nt][0], o[nt][1]);
        *(float2*)&Ob[(size_t)rowB * DD + col] = make_float2(o[nt][2], o[nt][3]);
    }
}

// ---------------------------------------------------------------------------
extern "C" void kernel_launch(void* const* d_in, const int* in_sizes, int n_in,
                              void* d_out, int out_size) {
    (void)in_sizes; (void)n_in; (void)out_size;
    const float* mirror    = (const float*)d_in[0];
    const float* satellite = (const float*)d_in[1];
    const void*  mask      = d_in[2];
    const float* Wq1 = (const float*)d_in[3];
    const float* Wk1 = (const float*)d_in[4];
    const float* Wq2 = (const float*)d_in[5];
    const float* Wk2 = (const float*)d_in[6];
    float* sat_out = (float*)d_out;
    float* mir_out = (float*)d_out + BND;

    cudaFuncSetAttribute(gemm_T_kernel,   cudaFuncAttributeMaxDynamicSharedMemorySize, GT_SMEM);
    cudaFuncSetAttribute(gemm_K2C_kernel, cudaFuncAttributeMaxDynamicSharedMemorySize, GK_SMEM);
    cudaFuncSetAttribute(attn_kernel,     cudaFuncAttributeMaxDynamicSharedMemorySize, SMEM_ATTN);

    detect_mask_kernel<<<1, 256>>>((const unsigned int*)mask);
    decode_mask_kernel<<<(BB * NN + 255) / 256, 256>>>(mask);
    compact_kernel<<<BB, 256>>>();

    prep_w_kernel<<<dim3(128, 2), 128>>>(Wq1, Wk1, Wq2, Wk2);
    split_kernel<<<(int)((BND / 2 + 255) / 256), 256>>>(mirror);

    gemm_T_kernel<<<(BB * NN) / 128, 256, GT_SMEM>>>();
    stage1_kernel<<<(BB * NN) / 8, 256>>>(mirror, satellite, sat_out);
    gemm_K2C_kernel<<<(BB * NN) / 128, 256, GK_SMEM>>>();
    attn_kernel<<<dim3(NN / 64, BB), 256, SMEM_ATTN>>>(mir_out);
}